// round 15
// baseline (speedup 1.0000x reference)
#include <cuda_runtime.h>
#include <cstdint>

// ---------------- problem constants ----------------
#define SQ    4096          // sequence length
#define EMBD  256
#define HDIRD 256           // HID/2
#define NG    1024          // 4*HDIR
#define TAGS  10
#define NEGV  -10000.0f
#define CL    8             // cluster size per direction
#define HPAD  132           // padded half stride in floats (128+4 -> halves in different banks)
#define HBSTR 264           // one buffer = 2 halves = 264 floats

// ---------------- scratch (device globals; no dynamic alloc) ----------------
__device__ float g_x[SQ * EMBD];              // gathered embeddings   4 MB
__device__ float g_xw[2][SQ * NG];            // input-gate precompute 32 MB
__device__ float g_h[2][SQ * HDIRD];          // hidden states         8 MB
__device__ float g_feats[SQ * TAGS];          // CRF emission feats

// ---------------- helpers ----------------
__device__ __forceinline__ uint32_t smem_u32(const void* p) {
    return (uint32_t)__cvta_generic_to_shared(p);
}
__device__ __forceinline__ uint32_t mapa_u32(uint32_t laddr, uint32_t rank) {
    uint32_t rem;
    asm("mapa.shared::cluster.u32 %0, %1, %2;" : "=r"(rem) : "r"(laddr), "r"(rank));
    return rem;
}
// remote store with completion tx delivered to the DESTINATION CTA's mbarrier
__device__ __forceinline__ void st_async_f32(uint32_t raddr, float v, uint32_t rmbar) {
    asm volatile(
        "st.async.shared::cluster.mbarrier::complete_tx::bytes.b32 [%0], %1, [%2];"
        :: "r"(raddr), "r"(__float_as_uint(v)), "r"(rmbar) : "memory");
}
__device__ __forceinline__ void mbar_init(uint32_t a, uint32_t cnt) {
    asm volatile("mbarrier.init.shared.b64 [%0], %1;" :: "r"(a), "r"(cnt) : "memory");
}
__device__ __forceinline__ void mbar_expect_tx(uint32_t a, uint32_t bytes) {
    asm volatile("mbarrier.arrive.expect_tx.shared.b64 _, [%0], %1;"
                 :: "r"(a), "r"(bytes) : "memory");
}
// exact known-good wait form from ptx_helpers.cuh (local CTA scope)
__device__ __forceinline__ void mbar_wait(uint32_t a, uint32_t par) {
    uint32_t done;
    asm volatile(
        "{\n\t.reg .pred p;\n\t"
        "mbarrier.try_wait.parity.acquire.cta.shared::cta.b64 p, [%1], %2;\n\t"
        "selp.b32 %0, 1, 0, p;\n\t}"
        : "=r"(done) : "r"(a), "r"(par) : "memory");
    if (!done) {
        asm volatile(
            "{\n\t.reg .pred P1;\n\t"
            "WAIT_LOOP_%=:\n\t"
            "mbarrier.try_wait.parity.acquire.cta.shared::cta.b64 P1, [%0], %1, 0x989680;\n\t"
            "@P1 bra.uni WAIT_DONE_%=;\n\t"
            "bra.uni WAIT_LOOP_%=;\n\t"
            "WAIT_DONE_%=:\n\t}"
            :: "r"(a), "r"(par) : "memory");
    }
}
#define CLUSTER_SYNC_() do {                                                   \
    asm volatile("barrier.cluster.arrive.aligned;" ::: "memory");              \
    asm volatile("barrier.cluster.wait.aligned;"   ::: "memory");              \
} while (0)

__device__ __forceinline__ void fma2(unsigned long long& d,
                                     unsigned long long a, unsigned long long b) {
    asm("fma.rn.f32x2 %0, %1, %2, %0;" : "+l"(d) : "l"(a), "l"(b));
}

__device__ __forceinline__ float sigm_f(float x) {
    return 1.0f / (1.0f + __expf(-x));
}
__device__ __forceinline__ float tanh_f(float x) {
    float e = __expf(-2.0f * fabsf(x));
    float r = (1.0f - e) / (1.0f + e);
    return copysignf(r, x);
}

// ---------------- kernel 1: embedding gather ----------------
__global__ void gather_k(const int* __restrict__ sent, const float* __restrict__ emb) {
    int gid = blockIdx.x * blockDim.x + threadIdx.x;  // over SQ*64 float4
    int row = gid >> 6;
    int c   = gid & 63;
    ((float4*)g_x)[row * 64 + c] =
        ((const float4*)emb)[(size_t)sent[row] * 64 + c];
}

// ---------------- kernel 2: xw = x @ Wih^T + (bih+bhh), both directions ----------------
// float4 global loads for both tiles, float4 global store for the output;
// the FMA loop and summation order are unchanged (bit-identical results).
__global__ void xw_gemm_k(const float* __restrict__ Wf, const float* __restrict__ Wb,
                          const float* __restrict__ bihf, const float* __restrict__ bhhf,
                          const float* __restrict__ bihb, const float* __restrict__ bhhb) {
    int d = blockIdx.z;
    const float* W  = d ? Wb : Wf;
    const float* b1 = d ? bihb : bihf;
    const float* b2 = d ? bhhb : bhhf;

    __shared__ float As[32][65];
    __shared__ float Bs[32][65];

    int s0 = blockIdx.x * 64;
    int j0 = blockIdx.y * 64;
    int tid = threadIdx.x;
    int tx = tid & 15, ty = tid >> 4;

    float acc[4][4];
#pragma unroll
    for (int i = 0; i < 4; i++)
#pragma unroll
        for (int j = 0; j < 4; j++) acc[i][j] = 0.0f;

    for (int k0 = 0; k0 < EMBD; k0 += 32) {
        // 512 float4 per tile / 256 threads = 2 per thread per tile
#pragma unroll
        for (int i = 0; i < 2; i++) {
            int idx = i * 256 + tid;         // 0..511
            int si = idx >> 3;               // 0..63
            int e4 = idx & 7;                // 0..7  (e = 4*e4..4*e4+3)
            float4 xa = *(const float4*)&g_x[(s0 + si) * EMBD + k0 + e4 * 4];
            As[e4 * 4 + 0][si] = xa.x;
            As[e4 * 4 + 1][si] = xa.y;
            As[e4 * 4 + 2][si] = xa.z;
            As[e4 * 4 + 3][si] = xa.w;
            float4 wb = *(const float4*)&W[(j0 + si) * EMBD + k0 + e4 * 4];
            Bs[e4 * 4 + 0][si] = wb.x;
            Bs[e4 * 4 + 1][si] = wb.y;
            Bs[e4 * 4 + 2][si] = wb.z;
            Bs[e4 * 4 + 3][si] = wb.w;
        }
        __syncthreads();
#pragma unroll
        for (int e = 0; e < 32; e++) {
            float a[4], bb[4];
#pragma unroll
            for (int i = 0; i < 4; i++) { a[i] = As[e][ty * 4 + i]; bb[i] = Bs[e][tx * 4 + i]; }
#pragma unroll
            for (int i = 0; i < 4; i++)
#pragma unroll
                for (int j = 0; j < 4; j++) acc[i][j] = fmaf(a[i], bb[j], acc[i][j]);
        }
        __syncthreads();
    }
#pragma unroll
    for (int i = 0; i < 4; i++) {
        int jj = j0 + tx * 4;
        float4 o;
        o.x = acc[i][0] + b1[jj + 0] + b2[jj + 0];
        o.y = acc[i][1] + b1[jj + 1] + b2[jj + 1];
        o.z = acc[i][2] + b1[jj + 2] + b2[jj + 2];
        o.w = acc[i][3] + b1[jj + 3] + b2[jj + 3];
        *(float4*)&g_xw[d][(s0 + ty * 4 + i) * NG + jj] = o;
    }
}

// ---------------- kernel 3: recurrent LSTM, one 8-CTA cluster per direction ----------------
// Exact R10 (best measured): scalar st.async fan-out with complete_tx,
// expect_tx 1024 B/phase, local acquire waits, parity double buffer.
__global__ void __cluster_dims__(CL, 1, 1) __launch_bounds__(256, 1)
lstm_k(const float* __restrict__ Whhf, const float* __restrict__ Whhb) {
    int dir = blockIdx.y;
    const float* Whh = dir ? Whhb : Whhf;
    const float* xw  = g_xw[dir];
    int r   = blockIdx.x;           // cluster rank
    int tid = threadIdx.x;
    int rr   = tid >> 1;            // 0..127 local row
    int half = tid & 1;             // column half
    int gate = rr >> 5;
    int j5   = rr & 31;
    int grow = gate * HDIRD + r * 32 + j5;   // global Whh row / xw column

    // weights -> registers, packed as f32 pairs (half row = 128 cols)
    ulonglong2 Wp[32];
    const ulonglong2* wsrc =
        (const ulonglong2*)(Whh + (size_t)grow * HDIRD + half * 128);
#pragma unroll
    for (int k = 0; k < 32; k++) Wp[k] = wsrc[k];

    __shared__ __align__(16) float hbuf[2 * HBSTR];   // halves padded by 16B
    __shared__ float zbuf[128];
    __shared__ __align__(8) unsigned long long mbs[2]; // mbar per buffer

    for (int i = tid; i < 2 * HBSTR; i += 256) hbuf[i] = 0.0f;
    uint32_t mbb = smem_u32(mbs);
    if (tid == 0) {
        mbar_init(mbb + 0, 1);
        mbar_init(mbb + 8, 1);
    }
    __syncthreads();
    CLUSTER_SYNC_();   // zeroed hbuf + initialized mbarriers visible cluster-wide

    // hoisted remote addresses (used by tid<32): data slot + destination mbar
    uint32_t hb0 = smem_u32(hbuf);
    uint32_t hoff4 = (uint32_t)(r * 32 + (tid & 31) + ((r >= 4) ? 4 : 0)) * 4u;
    uint32_t rh[CL], rmb[CL];
#pragma unroll
    for (int rk = 0; rk < CL; rk++) {
        rh[rk]  = mapa_u32(hb0, rk) + hoff4;
        rmb[rk] = mapa_u32(mbb, rk);
    }

    float c = 0.0f;
    float xwreg = 0.0f;
    int pos0 = dir ? (SQ - 1) : 0;
    if (!half) xwreg = xw[(size_t)pos0 * NG + grow];

    for (int t = 0; t < SQ; t++) {
        int p = t & 1;
        int tn = t + 1;

        // post this phase's expectation for the buffer being filled (p^1)
        if (tid == 0 && tn < SQ)
            mbar_expect_tx(mbb + (uint32_t)((p ^ 1) * 8), 1024u);
        // wait for buffer p to be complete (skip first step: zero-initialized)
        if (t) mbar_wait(mbb + (uint32_t)(p * 8), (uint32_t)(((t - 1) >> 1) & 1));
        __syncthreads();   // all warps see completed buffer; zbuf safe to rewrite

        const ulonglong2* h2 =
            (const ulonglong2*)(hbuf + p * HBSTR + half * HPAD);
        unsigned long long a0 = 0ull, a1 = 0ull;
#pragma unroll
        for (int k = 0; k < 32; k++) {
            ulonglong2 hv = h2[k];
            fma2(a0, Wp[k].x, hv.x);
            fma2(a1, Wp[k].y, hv.y);
        }
        float2 f0 = *(float2*)&a0;
        float2 f1 = *(float2*)&a1;
        float acc = (f0.x + f0.y) + (f1.x + f1.y);
        acc += __shfl_xor_sync(0xffffffffu, acc, 1);   // combine column halves
        if (!half) zbuf[rr] = acc + xwreg;

        // prefetch next step's xw
        if (!half && tn < SQ) {
            int pos = dir ? (SQ - 1 - tn) : tn;
            xwreg = xw[(size_t)pos * NG + grow];
        }
        __syncthreads();   // zbuf ready

        if (tid < 32) {
            float zi = zbuf[tid], zf = zbuf[32 + tid];
            float zg = zbuf[64 + tid], zo = zbuf[96 + tid];
            float ig = sigm_f(zi);
            float fg = sigm_f(zf);
            float gg = tanh_f(zg);
            float og = sigm_f(zo);
            c = fmaf(fg, c, ig * gg);
            float hn = og * tanh_f(c);

            int pos = dir ? (SQ - 1 - t) : t;
            g_h[dir][(size_t)pos * HDIRD + r * 32 + tid] = hn;

            if (tn < SQ) {   // data + completion to every rank (self included)
                uint32_t bo  = (uint32_t)((p ^ 1) * HBSTR * 4);
                uint32_t mbo = (uint32_t)((p ^ 1) * 8);
#pragma unroll
                for (int rk = 0; rk < CL; rk++)
                    st_async_f32(rh[rk] + bo, hn, rmb[rk] + mbo);
            }
        }
        // NO cluster.sync: next iteration's mbar_wait provides ordering.
    }
    CLUSTER_SYNC_();   // keep SMEM alive until all peers are done
}

// ---------------- kernel 4: feats = [h_f | h_b] @ Wout^T + b (warp per s) ----------------
__global__ void feats_k(const float* __restrict__ Wout, const float* __restrict__ bout) {
    __shared__ float Wsm[TAGS][512];
    __shared__ float bsm[TAGS];
    int tid = threadIdx.x;
    for (int i = tid; i < TAGS * 512; i += 256) Wsm[i / 512][i % 512] = Wout[i];
    if (tid < TAGS) bsm[tid] = bout[tid];
    __syncthreads();

    int lane = tid & 31;
    int s = blockIdx.x * 8 + (tid >> 5);     // warp per sequence position
    float acc[TAGS];
#pragma unroll
    for (int t = 0; t < TAGS; t++) acc[t] = 0.0f;

#pragma unroll
    for (int d = 0; d < 2; d++) {
        const float* hrow = (d == 0) ? &g_h[0][(size_t)s * HDIRD]
                                     : &g_h[1][(size_t)s * HDIRD];
#pragma unroll
        for (int k0 = 0; k0 < HDIRD; k0 += 32) {
            float x = hrow[k0 + lane];
#pragma unroll
            for (int t = 0; t < TAGS; t++)
                acc[t] = fmaf(x, Wsm[t][d * 256 + k0 + lane], acc[t]);
        }
    }
#pragma unroll
    for (int t = 0; t < TAGS; t++) {
#pragma unroll
        for (int o = 16; o > 0; o >>= 1) acc[t] += __shfl_xor_sync(0xffffffffu, acc[t], o);
    }
    if (lane == 0) {
#pragma unroll
        for (int t = 0; t < TAGS; t++) g_feats[s * TAGS + t] = acc[t] + bsm[t];
    }
}

// ---------------- kernel 5: Viterbi decode (single warp, tree argmax) ----------------
// argmax via FMNMX max-tree + equality bitmask + ffs: exact first-max
// semantics (fmaxf propagates an exact input; ffs picks the smallest p),
// replacing the 10-deep serial predicate chain (13 cyc/hop).
__global__ void viterbi_k(const float* __restrict__ trans, float* __restrict__ out,
                          int out_size) {
    __shared__ unsigned char bp[SQ][TAGS];   // 40 KB backpointers
    int n = threadIdx.x;

    float tr[TAGS];
#pragma unroll
    for (int p = 0; p < TAGS; p++) tr[p] = (n < TAGS) ? trans[n * TAGS + p] : NEGV;

    float fvr = (n == 8) ? 0.0f : NEGV;      // START = 8
    float fa = (n < TAGS) ? g_feats[0 * TAGS + n] : 0.0f;
    float fb = (n < TAGS) ? g_feats[1 * TAGS + n] : 0.0f;

    for (int t = 0; t < SQ; t++) {
        float v[TAGS];
#pragma unroll
        for (int p = 0; p < TAGS; p++)
            v[p] = __shfl_sync(0xffffffffu, fvr, p) + tr[p];

        // max tree (depth 4)
        float m01 = fmaxf(v[0], v[1]);
        float m23 = fmaxf(v[2], v[3]);
        float m45 = fmaxf(v[4], v[5]);
        float m67 = fmaxf(v[6], v[7]);
        float m89 = fmaxf(v[8], v[9]);
        float m = fmaxf(fmaxf(fmaxf(m01, m23), fmaxf(m45, m67)), m89);

        // first index achieving the max (parallel compares + ffs)
        unsigned mk = 0;
#pragma unroll
        for (int p = 0; p < TAGS; p++) mk |= (v[p] == m) ? (1u << p) : 0u;
        int bi = __ffs(mk) - 1;

        if (n < TAGS) bp[t][n] = (unsigned char)bi;
        float nf = m + fa;
        fa = fb;
        int tn = t + 2;
        if (n < TAGS && tn < SQ) fb = g_feats[tn * TAGS + n];
        fvr = nf;
    }

    float term = fvr + ((n < TAGS) ? trans[9 * TAGS + n] : NEGV);
    float bm = -3.4e38f;
    int bidx = 0;
#pragma unroll
    for (int p = 0; p < TAGS; p++) {
        float v = __shfl_sync(0xffffffffu, term, p);
        if (v > bm) { bm = v; bidx = p; }
    }
    if (n == 0) {
        int off = (out_size > SQ) ? 1 : 0;
        if (off) out[0] = bm;                // score first, then path
        int tag = bidx;
        for (int t = SQ - 1; t >= 0; t--) {
            out[off + t] = (float)tag;
            tag = bp[t][tag];
        }
    }
}

// ---------------- launch ----------------
extern "C" void kernel_launch(void* const* d_in, const int* in_sizes, int n_in,
                              void* d_out, int out_size) {
    const int*   sent  = (const int*)d_in[0];
    const float* emb   = (const float*)d_in[1];
    const float* Wih_f = (const float*)d_in[2];
    const float* Whh_f = (const float*)d_in[3];
    const float* bih_f = (const float*)d_in[4];
    const float* bhh_f = (const float*)d_in[5];
    const float* Wih_b = (const float*)d_in[6];
    const float* Whh_b = (const float*)d_in[7];
    const float* bih_b = (const float*)d_in[8];
    const float* bhh_b = (const float*)d_in[9];
    const float* W_out = (const float*)d_in[10];
    const float* b_out = (const float*)d_in[11];
    const float* trans = (const float*)d_in[12];
    float* out = (float*)d_out;

    gather_k<<<(SQ * 64) / 256, 256>>>(sent, emb);
    xw_gemm_k<<<dim3(SQ / 64, NG / 64, 2), 256>>>(Wih_f, Wih_b, bih_f, bhh_f, bih_b, bhh_b);
    lstm_k<<<dim3(CL, 2, 1), 256>>>(Whh_f, Whh_b);
    feats_k<<<SQ / 8, 256>>>(W_out, b_out);   // 512 blocks x 8 warps = 4096 positions
    viterbi_k<<<1, 32>>>(trans, out, out_size);
}

// round 16
// speedup vs baseline: 1.0005x; 1.0005x over previous
#include <cuda_runtime.h>
#include <cstdint>

// ---------------- problem constants ----------------
#define SQ    4096          // sequence length
#define EMBD  256
#define HDIRD 256           // HID/2
#define NG    1024          // 4*HDIR
#define TAGS  10
#define NEGV  -10000.0f
#define CL    8             // cluster size per direction
#define HPAD  132           // padded half stride in floats (128+4 -> halves in different banks)
#define HBSTR 264           // one buffer = 2 halves = 264 floats

// ---------------- scratch (device globals; no dynamic alloc) ----------------
__device__ float g_x[SQ * EMBD];              // gathered embeddings   4 MB
__device__ float g_xw[2][SQ * NG];            // input-gate precompute 32 MB
__device__ float g_h[2][SQ * HDIRD];          // hidden states         8 MB
__device__ float g_feats[SQ * TAGS];          // CRF emission feats

// ---------------- helpers ----------------
__device__ __forceinline__ uint32_t smem_u32(const void* p) {
    return (uint32_t)__cvta_generic_to_shared(p);
}
__device__ __forceinline__ uint32_t mapa_u32(uint32_t laddr, uint32_t rank) {
    uint32_t rem;
    asm("mapa.shared::cluster.u32 %0, %1, %2;" : "=r"(rem) : "r"(laddr), "r"(rank));
    return rem;
}
// remote store with completion tx delivered to the DESTINATION CTA's mbarrier
__device__ __forceinline__ void st_async_f32(uint32_t raddr, float v, uint32_t rmbar) {
    asm volatile(
        "st.async.shared::cluster.mbarrier::complete_tx::bytes.b32 [%0], %1, [%2];"
        :: "r"(raddr), "r"(__float_as_uint(v)), "r"(rmbar) : "memory");
}
__device__ __forceinline__ void mbar_init(uint32_t a, uint32_t cnt) {
    asm volatile("mbarrier.init.shared.b64 [%0], %1;" :: "r"(a), "r"(cnt) : "memory");
}
__device__ __forceinline__ void mbar_expect_tx(uint32_t a, uint32_t bytes) {
    asm volatile("mbarrier.arrive.expect_tx.shared.b64 _, [%0], %1;"
                 :: "r"(a), "r"(bytes) : "memory");
}
// exact known-good wait form from ptx_helpers.cuh (local CTA scope)
__device__ __forceinline__ void mbar_wait(uint32_t a, uint32_t par) {
    uint32_t done;
    asm volatile(
        "{\n\t.reg .pred p;\n\t"
        "mbarrier.try_wait.parity.acquire.cta.shared::cta.b64 p, [%1], %2;\n\t"
        "selp.b32 %0, 1, 0, p;\n\t}"
        : "=r"(done) : "r"(a), "r"(par) : "memory");
    if (!done) {
        asm volatile(
            "{\n\t.reg .pred P1;\n\t"
            "WAIT_LOOP_%=:\n\t"
            "mbarrier.try_wait.parity.acquire.cta.shared::cta.b64 P1, [%0], %1, 0x989680;\n\t"
            "@P1 bra.uni WAIT_DONE_%=;\n\t"
            "bra.uni WAIT_LOOP_%=;\n\t"
            "WAIT_DONE_%=:\n\t}"
            :: "r"(a), "r"(par) : "memory");
    }
}
#define CLUSTER_SYNC_() do {                                                   \
    asm volatile("barrier.cluster.arrive.aligned;" ::: "memory");              \
    asm volatile("barrier.cluster.wait.aligned;"   ::: "memory");              \
} while (0)

__device__ __forceinline__ void fma2(unsigned long long& d,
                                     unsigned long long a, unsigned long long b) {
    asm("fma.rn.f32x2 %0, %1, %2, %0;" : "+l"(d) : "l"(a), "l"(b));
}

__device__ __forceinline__ float sigm_f(float x) {
    return 1.0f / (1.0f + __expf(-x));
}
__device__ __forceinline__ float tanh_f(float x) {
    float e = __expf(-2.0f * fabsf(x));
    float r = (1.0f - e) / (1.0f + e);
    return copysignf(r, x);
}

// ---------------- kernel 1: embedding gather ----------------
__global__ void gather_k(const int* __restrict__ sent, const float* __restrict__ emb) {
    int gid = blockIdx.x * blockDim.x + threadIdx.x;  // over SQ*64 float4
    int row = gid >> 6;
    int c   = gid & 63;
    ((float4*)g_x)[row * 64 + c] =
        ((const float4*)emb)[(size_t)sent[row] * 64 + c];
}

// ---------------- kernel 2: xw = x @ Wih^T + (bih+bhh), both directions ----------------
// (R10 version — participated in every best measurement)
__global__ void xw_gemm_k(const float* __restrict__ Wf, const float* __restrict__ Wb,
                          const float* __restrict__ bihf, const float* __restrict__ bhhf,
                          const float* __restrict__ bihb, const float* __restrict__ bhhb) {
    int d = blockIdx.z;
    const float* W  = d ? Wb : Wf;
    const float* b1 = d ? bihb : bihf;
    const float* b2 = d ? bhhb : bhhf;

    __shared__ float As[32][65];
    __shared__ float Bs[32][65];

    int s0 = blockIdx.x * 64;
    int j0 = blockIdx.y * 64;
    int tid = threadIdx.x;
    int tx = tid & 15, ty = tid >> 4;

    float acc[4][4];
#pragma unroll
    for (int i = 0; i < 4; i++)
#pragma unroll
        for (int j = 0; j < 4; j++) acc[i][j] = 0.0f;

    for (int k0 = 0; k0 < EMBD; k0 += 32) {
#pragma unroll
        for (int i = 0; i < 8; i++) {
            int idx = i * 256 + tid;
            int si = idx >> 5, e = idx & 31;
            As[e][si] = g_x[(s0 + si) * EMBD + k0 + e];
            Bs[e][si] = W[(j0 + si) * EMBD + k0 + e];
        }
        __syncthreads();
#pragma unroll
        for (int e = 0; e < 32; e++) {
            float a[4], bb[4];
#pragma unroll
            for (int i = 0; i < 4; i++) { a[i] = As[e][ty * 4 + i]; bb[i] = Bs[e][tx * 4 + i]; }
#pragma unroll
            for (int i = 0; i < 4; i++)
#pragma unroll
                for (int j = 0; j < 4; j++) acc[i][j] = fmaf(a[i], bb[j], acc[i][j]);
        }
        __syncthreads();
    }
#pragma unroll
    for (int i = 0; i < 4; i++)
#pragma unroll
        for (int j = 0; j < 4; j++) {
            int jj = j0 + tx * 4 + j;
            g_xw[d][(s0 + ty * 4 + i) * NG + jj] = acc[i][j] + b1[jj] + b2[jj];
        }
}

// ---------------- kernel 3: recurrent LSTM, one 8-CTA cluster per direction ----------------
// Exact R10 (best measured): scalar st.async fan-out with complete_tx,
// expect_tx 1024 B/phase, local acquire waits, parity double buffer.
__global__ void __cluster_dims__(CL, 1, 1) __launch_bounds__(256, 1)
lstm_k(const float* __restrict__ Whhf, const float* __restrict__ Whhb) {
    int dir = blockIdx.y;
    const float* Whh = dir ? Whhb : Whhf;
    const float* xw  = g_xw[dir];
    int r   = blockIdx.x;           // cluster rank
    int tid = threadIdx.x;
    int rr   = tid >> 1;            // 0..127 local row
    int half = tid & 1;             // column half
    int gate = rr >> 5;
    int j5   = rr & 31;
    int grow = gate * HDIRD + r * 32 + j5;   // global Whh row / xw column

    // weights -> registers, packed as f32 pairs (half row = 128 cols)
    ulonglong2 Wp[32];
    const ulonglong2* wsrc =
        (const ulonglong2*)(Whh + (size_t)grow * HDIRD + half * 128);
#pragma unroll
    for (int k = 0; k < 32; k++) Wp[k] = wsrc[k];

    __shared__ __align__(16) float hbuf[2 * HBSTR];   // halves padded by 16B
    __shared__ float zbuf[128];
    __shared__ __align__(8) unsigned long long mbs[2]; // mbar per buffer

    for (int i = tid; i < 2 * HBSTR; i += 256) hbuf[i] = 0.0f;
    uint32_t mbb = smem_u32(mbs);
    if (tid == 0) {
        mbar_init(mbb + 0, 1);
        mbar_init(mbb + 8, 1);
    }
    __syncthreads();
    CLUSTER_SYNC_();   // zeroed hbuf + initialized mbarriers visible cluster-wide

    // hoisted remote addresses (used by tid<32): data slot + destination mbar
    uint32_t hb0 = smem_u32(hbuf);
    uint32_t hoff4 = (uint32_t)(r * 32 + (tid & 31) + ((r >= 4) ? 4 : 0)) * 4u;
    uint32_t rh[CL], rmb[CL];
#pragma unroll
    for (int rk = 0; rk < CL; rk++) {
        rh[rk]  = mapa_u32(hb0, rk) + hoff4;
        rmb[rk] = mapa_u32(mbb, rk);
    }

    float c = 0.0f;
    float xwreg = 0.0f;
    int pos0 = dir ? (SQ - 1) : 0;
    if (!half) xwreg = xw[(size_t)pos0 * NG + grow];

    for (int t = 0; t < SQ; t++) {
        int p = t & 1;
        int tn = t + 1;

        // post this phase's expectation for the buffer being filled (p^1)
        if (tid == 0 && tn < SQ)
            mbar_expect_tx(mbb + (uint32_t)((p ^ 1) * 8), 1024u);
        // wait for buffer p to be complete (skip first step: zero-initialized)
        if (t) mbar_wait(mbb + (uint32_t)(p * 8), (uint32_t)(((t - 1) >> 1) & 1));
        __syncthreads();   // all warps see completed buffer; zbuf safe to rewrite

        const ulonglong2* h2 =
            (const ulonglong2*)(hbuf + p * HBSTR + half * HPAD);
        unsigned long long a0 = 0ull, a1 = 0ull;
#pragma unroll
        for (int k = 0; k < 32; k++) {
            ulonglong2 hv = h2[k];
            fma2(a0, Wp[k].x, hv.x);
            fma2(a1, Wp[k].y, hv.y);
        }
        float2 f0 = *(float2*)&a0;
        float2 f1 = *(float2*)&a1;
        float acc = (f0.x + f0.y) + (f1.x + f1.y);
        acc += __shfl_xor_sync(0xffffffffu, acc, 1);   // combine column halves
        if (!half) zbuf[rr] = acc + xwreg;

        // prefetch next step's xw
        if (!half && tn < SQ) {
            int pos = dir ? (SQ - 1 - tn) : tn;
            xwreg = xw[(size_t)pos * NG + grow];
        }
        __syncthreads();   // zbuf ready

        if (tid < 32) {
            float zi = zbuf[tid], zf = zbuf[32 + tid];
            float zg = zbuf[64 + tid], zo = zbuf[96 + tid];
            float ig = sigm_f(zi);
            float fg = sigm_f(zf);
            float gg = tanh_f(zg);
            float og = sigm_f(zo);
            c = fmaf(fg, c, ig * gg);
            float hn = og * tanh_f(c);

            int pos = dir ? (SQ - 1 - t) : t;
            g_h[dir][(size_t)pos * HDIRD + r * 32 + tid] = hn;

            if (tn < SQ) {   // data + completion to every rank (self included)
                uint32_t bo  = (uint32_t)((p ^ 1) * HBSTR * 4);
                uint32_t mbo = (uint32_t)((p ^ 1) * 8);
#pragma unroll
                for (int rk = 0; rk < CL; rk++)
                    st_async_f32(rh[rk] + bo, hn, rmb[rk] + mbo);
            }
        }
        // NO cluster.sync: next iteration's mbar_wait provides ordering.
    }
    CLUSTER_SYNC_();   // keep SMEM alive until all peers are done
}

// ---------------- kernel 4: feats = [h_f | h_b] @ Wout^T + b (warp per s) ----------------
__global__ void feats_k(const float* __restrict__ Wout, const float* __restrict__ bout) {
    __shared__ float Wsm[TAGS][512];
    __shared__ float bsm[TAGS];
    int tid = threadIdx.x;
    for (int i = tid; i < TAGS * 512; i += 256) Wsm[i / 512][i % 512] = Wout[i];
    if (tid < TAGS) bsm[tid] = bout[tid];
    __syncthreads();

    int lane = tid & 31;
    int s = blockIdx.x * 8 + (tid >> 5);     // warp per sequence position
    float acc[TAGS];
#pragma unroll
    for (int t = 0; t < TAGS; t++) acc[t] = 0.0f;

#pragma unroll
    for (int d = 0; d < 2; d++) {
        const float* hrow = (d == 0) ? &g_h[0][(size_t)s * HDIRD]
                                     : &g_h[1][(size_t)s * HDIRD];
#pragma unroll
        for (int k0 = 0; k0 < HDIRD; k0 += 32) {
            float x = hrow[k0 + lane];
#pragma unroll
            for (int t = 0; t < TAGS; t++)
                acc[t] = fmaf(x, Wsm[t][d * 256 + k0 + lane], acc[t]);
        }
    }
#pragma unroll
    for (int t = 0; t < TAGS; t++) {
#pragma unroll
        for (int o = 16; o > 0; o >>= 1) acc[t] += __shfl_xor_sync(0xffffffffu, acc[t], o);
    }
    if (lane == 0) {
#pragma unroll
        for (int t = 0; t < TAGS; t++) g_feats[s * TAGS + t] = acc[t] + bsm[t];
    }
}

// ---------------- kernel 5: Viterbi decode (single warp, tree argmax) ----------------
// argmax via fmaxf tree + equality bitmask + ffs: exact first-max semantics
// (fmaxf propagates an exact input value; ffs picks the smallest index),
// replacing the 10-deep serial predicate chain (13 cyc/hop).
__global__ void viterbi_k(const float* __restrict__ trans, float* __restrict__ out,
                          int out_size) {
    __shared__ unsigned char bp[SQ][TAGS];   // 40 KB backpointers
    int n = threadIdx.x;

    float tr[TAGS];
#pragma unroll
    for (int p = 0; p < TAGS; p++) tr[p] = (n < TAGS) ? trans[n * TAGS + p] : NEGV;

    float fvr = (n == 8) ? 0.0f : NEGV;      // START = 8
    float fa = (n < TAGS) ? g_feats[0 * TAGS + n] : 0.0f;
    float fb = (n < TAGS) ? g_feats[1 * TAGS + n] : 0.0f;

    for (int t = 0; t < SQ; t++) {
        float v[TAGS];
#pragma unroll
        for (int p = 0; p < TAGS; p++)
            v[p] = __shfl_sync(0xffffffffu, fvr, p) + tr[p];

        // max tree (depth 4)
        float m01 = fmaxf(v[0], v[1]);
        float m23 = fmaxf(v[2], v[3]);
        float m45 = fmaxf(v[4], v[5]);
        float m67 = fmaxf(v[6], v[7]);
        float m89 = fmaxf(v[8], v[9]);
        float m = fmaxf(fmaxf(fmaxf(m01, m23), fmaxf(m45, m67)), m89);

        // first index achieving the max (parallel compares + ffs)
        unsigned mk = 0;
#pragma unroll
        for (int p = 0; p < TAGS; p++) mk |= (v[p] == m) ? (1u << p) : 0u;
        int bi = __ffs(mk) - 1;

        if (n < TAGS) bp[t][n] = (unsigned char)bi;
        float nf = m + fa;
        fa = fb;
        int tn = t + 2;
        if (n < TAGS && tn < SQ) fb = g_feats[tn * TAGS + n];
        fvr = nf;
    }

    float term = fvr + ((n < TAGS) ? trans[9 * TAGS + n] : NEGV);
    float bm = -3.4e38f;
    int bidx = 0;
#pragma unroll
    for (int p = 0; p < TAGS; p++) {
        float v = __shfl_sync(0xffffffffu, term, p);
        if (v > bm) { bm = v; bidx = p; }
    }
    if (n == 0) {
        int off = (out_size > SQ) ? 1 : 0;
        if (off) out[0] = bm;                // score first, then path
        int tag = bidx;
        for (int t = SQ - 1; t >= 0; t--) {
            out[off + t] = (float)tag;
            tag = bp[t][tag];
        }
    }
}

// ---------------- launch ----------------
extern "C" void kernel_launch(void* const* d_in, const int* in_sizes, int n_in,
                              void* d_out, int out_size) {
    const int*   sent  = (const int*)d_in[0];
    const float* emb   = (const float*)d_in[1];
    const float* Wih_f = (const float*)d_in[2];
    const float* Whh_f = (const float*)d_in[3];
    const float* bih_f = (const float*)d_in[4];
    const float* bhh_f = (const float*)d_in[5];
    const float* Wih_b = (const float*)d_in[6];
    const float* Whh_b = (const float*)d_in[7];
    const float* bih_b = (const float*)d_in[8];
    const float* bhh_b = (const float*)d_in[9];
    const float* W_out = (const float*)d_in[10];
    const float* b_out = (const float*)d_in[11];
    const float* trans = (const float*)d_in[12];
    float* out = (float*)d_out;

    gather_k<<<(SQ * 64) / 256, 256>>>(sent, emb);
    xw_gemm_k<<<dim3(SQ / 64, NG / 64, 2), 256>>>(Wih_f, Wih_b, bih_f, bhh_f, bih_b, bhh_b);
    lstm_k<<<dim3(CL, 2, 1), 256>>>(Whh_f, Whh_b);
    feats_k<<<SQ / 8, 256>>>(W_out, b_out);   // 512 blocks x 8 warps = 4096 positions
    viterbi_k<<<1, 32>>>(trans, out, out_size);
}

// round 17
// speedup vs baseline: 1.0985x; 1.0979x over previous
#include <cuda_runtime.h>
#include <cstdint>

// ---------------- problem constants ----------------
#define SQ    4096          // sequence length
#define EMBD  256
#define HDIRD 256           // HID/2
#define NG    1024          // 4*HDIR
#define TAGS  10
#define NEGV  -10000.0f
#define CL    8             // cluster size per direction
#define HPAD  132           // padded half stride in floats (128+4 -> halves in different banks)
#define HBSTR 264           // one buffer = 2 halves = 264 floats
#define VNW   32            // viterbi replay warps
#define VCH   (SQ / VNW)    // 128 steps per chunk

// ---------------- scratch (device globals; no dynamic alloc) ----------------
__device__ float g_x[SQ * EMBD];              // gathered embeddings   4 MB
__device__ float g_xw[2][SQ * NG];            // input-gate precompute 32 MB
__device__ float g_h[2][SQ * HDIRD];          // hidden states         8 MB
__device__ float g_feats[SQ * TAGS];          // CRF emission feats

// ---------------- helpers ----------------
__device__ __forceinline__ uint32_t smem_u32(const void* p) {
    return (uint32_t)__cvta_generic_to_shared(p);
}
__device__ __forceinline__ uint32_t mapa_u32(uint32_t laddr, uint32_t rank) {
    uint32_t rem;
    asm("mapa.shared::cluster.u32 %0, %1, %2;" : "=r"(rem) : "r"(laddr), "r"(rank));
    return rem;
}
// remote store with completion tx delivered to the DESTINATION CTA's mbarrier
__device__ __forceinline__ void st_async_f32(uint32_t raddr, float v, uint32_t rmbar) {
    asm volatile(
        "st.async.shared::cluster.mbarrier::complete_tx::bytes.b32 [%0], %1, [%2];"
        :: "r"(raddr), "r"(__float_as_uint(v)), "r"(rmbar) : "memory");
}
__device__ __forceinline__ void mbar_init(uint32_t a, uint32_t cnt) {
    asm volatile("mbarrier.init.shared.b64 [%0], %1;" :: "r"(a), "r"(cnt) : "memory");
}
__device__ __forceinline__ void mbar_expect_tx(uint32_t a, uint32_t bytes) {
    asm volatile("mbarrier.arrive.expect_tx.shared.b64 _, [%0], %1;"
                 :: "r"(a), "r"(bytes) : "memory");
}
// exact known-good wait form from ptx_helpers.cuh (local CTA scope)
__device__ __forceinline__ void mbar_wait(uint32_t a, uint32_t par) {
    uint32_t done;
    asm volatile(
        "{\n\t.reg .pred p;\n\t"
        "mbarrier.try_wait.parity.acquire.cta.shared::cta.b64 p, [%1], %2;\n\t"
        "selp.b32 %0, 1, 0, p;\n\t}"
        : "=r"(done) : "r"(a), "r"(par) : "memory");
    if (!done) {
        asm volatile(
            "{\n\t.reg .pred P1;\n\t"
            "WAIT_LOOP_%=:\n\t"
            "mbarrier.try_wait.parity.acquire.cta.shared::cta.b64 P1, [%0], %1, 0x989680;\n\t"
            "@P1 bra.uni WAIT_DONE_%=;\n\t"
            "bra.uni WAIT_LOOP_%=;\n\t"
            "WAIT_DONE_%=:\n\t}"
            :: "r"(a), "r"(par) : "memory");
    }
}
#define CLUSTER_SYNC_() do {                                                   \
    asm volatile("barrier.cluster.arrive.aligned;" ::: "memory");              \
    asm volatile("barrier.cluster.wait.aligned;"   ::: "memory");              \
} while (0)

__device__ __forceinline__ void fma2(unsigned long long& d,
                                     unsigned long long a, unsigned long long b) {
    asm("fma.rn.f32x2 %0, %1, %2, %0;" : "+l"(d) : "l"(a), "l"(b));
}

__device__ __forceinline__ float sigm_f(float x) {
    return 1.0f / (1.0f + __expf(-x));
}
__device__ __forceinline__ float tanh_f(float x) {
    float e = __expf(-2.0f * fabsf(x));
    float r = (1.0f - e) / (1.0f + e);
    return copysignf(r, x);
}

// exact 10-way max tree (max is associative exactly; result bit-identical to
// any evaluation order, and equals one of the inputs)
__device__ __forceinline__ float max10(const float* v) {
    float m01 = fmaxf(v[0], v[1]);
    float m23 = fmaxf(v[2], v[3]);
    float m45 = fmaxf(v[4], v[5]);
    float m67 = fmaxf(v[6], v[7]);
    float m89 = fmaxf(v[8], v[9]);
    return fmaxf(fmaxf(fmaxf(m01, m23), fmaxf(m45, m67)), m89);
}

// ---------------- kernel 1: embedding gather ----------------
__global__ void gather_k(const int* __restrict__ sent, const float* __restrict__ emb) {
    int gid = blockIdx.x * blockDim.x + threadIdx.x;  // over SQ*64 float4
    int row = gid >> 6;
    int c   = gid & 63;
    ((float4*)g_x)[row * 64 + c] =
        ((const float4*)emb)[(size_t)sent[row] * 64 + c];
}

// ---------------- kernel 2: xw = x @ Wih^T + (bih+bhh), both directions ----------------
// (R10 version — participated in every best measurement)
__global__ void xw_gemm_k(const float* __restrict__ Wf, const float* __restrict__ Wb,
                          const float* __restrict__ bihf, const float* __restrict__ bhhf,
                          const float* __restrict__ bihb, const float* __restrict__ bhhb) {
    int d = blockIdx.z;
    const float* W  = d ? Wb : Wf;
    const float* b1 = d ? bihb : bihf;
    const float* b2 = d ? bhhb : bhhf;

    __shared__ float As[32][65];
    __shared__ float Bs[32][65];

    int s0 = blockIdx.x * 64;
    int j0 = blockIdx.y * 64;
    int tid = threadIdx.x;
    int tx = tid & 15, ty = tid >> 4;

    float acc[4][4];
#pragma unroll
    for (int i = 0; i < 4; i++)
#pragma unroll
        for (int j = 0; j < 4; j++) acc[i][j] = 0.0f;

    for (int k0 = 0; k0 < EMBD; k0 += 32) {
#pragma unroll
        for (int i = 0; i < 8; i++) {
            int idx = i * 256 + tid;
            int si = idx >> 5, e = idx & 31;
            As[e][si] = g_x[(s0 + si) * EMBD + k0 + e];
            Bs[e][si] = W[(j0 + si) * EMBD + k0 + e];
        }
        __syncthreads();
#pragma unroll
        for (int e = 0; e < 32; e++) {
            float a[4], bb[4];
#pragma unroll
            for (int i = 0; i < 4; i++) { a[i] = As[e][ty * 4 + i]; bb[i] = Bs[e][tx * 4 + i]; }
#pragma unroll
            for (int i = 0; i < 4; i++)
#pragma unroll
                for (int j = 0; j < 4; j++) acc[i][j] = fmaf(a[i], bb[j], acc[i][j]);
        }
        __syncthreads();
    }
#pragma unroll
    for (int i = 0; i < 4; i++)
#pragma unroll
        for (int j = 0; j < 4; j++) {
            int jj = j0 + tx * 4 + j;
            g_xw[d][(s0 + ty * 4 + i) * NG + jj] = acc[i][j] + b1[jj] + b2[jj];
        }
}

// ---------------- kernel 3: recurrent LSTM, one 8-CTA cluster per direction ----------------
// Exact R10 (best measured): scalar st.async fan-out with complete_tx,
// expect_tx 1024 B/phase, local acquire waits, parity double buffer.
__global__ void __cluster_dims__(CL, 1, 1) __launch_bounds__(256, 1)
lstm_k(const float* __restrict__ Whhf, const float* __restrict__ Whhb) {
    int dir = blockIdx.y;
    const float* Whh = dir ? Whhb : Whhf;
    const float* xw  = g_xw[dir];
    int r   = blockIdx.x;           // cluster rank
    int tid = threadIdx.x;
    int rr   = tid >> 1;            // 0..127 local row
    int half = tid & 1;             // column half
    int gate = rr >> 5;
    int j5   = rr & 31;
    int grow = gate * HDIRD + r * 32 + j5;   // global Whh row / xw column

    // weights -> registers, packed as f32 pairs (half row = 128 cols)
    ulonglong2 Wp[32];
    const ulonglong2* wsrc =
        (const ulonglong2*)(Whh + (size_t)grow * HDIRD + half * 128);
#pragma unroll
    for (int k = 0; k < 32; k++) Wp[k] = wsrc[k];

    __shared__ __align__(16) float hbuf[2 * HBSTR];   // halves padded by 16B
    __shared__ float zbuf[128];
    __shared__ __align__(8) unsigned long long mbs[2]; // mbar per buffer

    for (int i = tid; i < 2 * HBSTR; i += 256) hbuf[i] = 0.0f;
    uint32_t mbb = smem_u32(mbs);
    if (tid == 0) {
        mbar_init(mbb + 0, 1);
        mbar_init(mbb + 8, 1);
    }
    __syncthreads();
    CLUSTER_SYNC_();   // zeroed hbuf + initialized mbarriers visible cluster-wide

    // hoisted remote addresses (used by tid<32): data slot + destination mbar
    uint32_t hb0 = smem_u32(hbuf);
    uint32_t hoff4 = (uint32_t)(r * 32 + (tid & 31) + ((r >= 4) ? 4 : 0)) * 4u;
    uint32_t rh[CL], rmb[CL];
#pragma unroll
    for (int rk = 0; rk < CL; rk++) {
        rh[rk]  = mapa_u32(hb0, rk) + hoff4;
        rmb[rk] = mapa_u32(mbb, rk);
    }

    float c = 0.0f;
    float xwreg = 0.0f;
    int pos0 = dir ? (SQ - 1) : 0;
    if (!half) xwreg = xw[(size_t)pos0 * NG + grow];

    for (int t = 0; t < SQ; t++) {
        int p = t & 1;
        int tn = t + 1;

        // post this phase's expectation for the buffer being filled (p^1)
        if (tid == 0 && tn < SQ)
            mbar_expect_tx(mbb + (uint32_t)((p ^ 1) * 8), 1024u);
        // wait for buffer p to be complete (skip first step: zero-initialized)
        if (t) mbar_wait(mbb + (uint32_t)(p * 8), (uint32_t)(((t - 1) >> 1) & 1));
        __syncthreads();   // all warps see completed buffer; zbuf safe to rewrite

        const ulonglong2* h2 =
            (const ulonglong2*)(hbuf + p * HBSTR + half * HPAD);
        unsigned long long a0 = 0ull, a1 = 0ull;
#pragma unroll
        for (int k = 0; k < 32; k++) {
            ulonglong2 hv = h2[k];
            fma2(a0, Wp[k].x, hv.x);
            fma2(a1, Wp[k].y, hv.y);
        }
        float2 f0 = *(float2*)&a0;
        float2 f1 = *(float2*)&a1;
        float acc = (f0.x + f0.y) + (f1.x + f1.y);
        acc += __shfl_xor_sync(0xffffffffu, acc, 1);   // combine column halves
        if (!half) zbuf[rr] = acc + xwreg;

        // prefetch next step's xw
        if (!half && tn < SQ) {
            int pos = dir ? (SQ - 1 - tn) : tn;
            xwreg = xw[(size_t)pos * NG + grow];
        }
        __syncthreads();   // zbuf ready

        if (tid < 32) {
            float zi = zbuf[tid], zf = zbuf[32 + tid];
            float zg = zbuf[64 + tid], zo = zbuf[96 + tid];
            float ig = sigm_f(zi);
            float fg = sigm_f(zf);
            float gg = tanh_f(zg);
            float og = sigm_f(zo);
            c = fmaf(fg, c, ig * gg);
            float hn = og * tanh_f(c);

            int pos = dir ? (SQ - 1 - t) : t;
            g_h[dir][(size_t)pos * HDIRD + r * 32 + tid] = hn;

            if (tn < SQ) {   // data + completion to every rank (self included)
                uint32_t bo  = (uint32_t)((p ^ 1) * HBSTR * 4);
                uint32_t mbo = (uint32_t)((p ^ 1) * 8);
#pragma unroll
                for (int rk = 0; rk < CL; rk++)
                    st_async_f32(rh[rk] + bo, hn, rmb[rk] + mbo);
            }
        }
        // NO cluster.sync: next iteration's mbar_wait provides ordering.
    }
    CLUSTER_SYNC_();   // keep SMEM alive until all peers are done
}

// ---------------- kernel 4: feats = [h_f | h_b] @ Wout^T + b (warp per s) ----------------
__global__ void feats_k(const float* __restrict__ Wout, const float* __restrict__ bout) {
    __shared__ float Wsm[TAGS][512];
    __shared__ float bsm[TAGS];
    int tid = threadIdx.x;
    for (int i = tid; i < TAGS * 512; i += 256) Wsm[i / 512][i % 512] = Wout[i];
    if (tid < TAGS) bsm[tid] = bout[tid];
    __syncthreads();

    int lane = tid & 31;
    int s = blockIdx.x * 8 + (tid >> 5);     // warp per sequence position
    float acc[TAGS];
#pragma unroll
    for (int t = 0; t < TAGS; t++) acc[t] = 0.0f;

#pragma unroll
    for (int d = 0; d < 2; d++) {
        const float* hrow = (d == 0) ? &g_h[0][(size_t)s * HDIRD]
                                     : &g_h[1][(size_t)s * HDIRD];
#pragma unroll
        for (int k0 = 0; k0 < HDIRD; k0 += 32) {
            float x = hrow[k0 + lane];
#pragma unroll
            for (int t = 0; t < TAGS; t++)
                acc[t] = fmaf(x, Wsm[t][d * 256 + k0 + lane], acc[t]);
        }
    }
#pragma unroll
    for (int t = 0; t < TAGS; t++) {
#pragma unroll
        for (int o = 16; o > 0; o >>= 1) acc[t] += __shfl_xor_sync(0xffffffffu, acc[t], o);
    }
    if (lane == 0) {
#pragma unroll
        for (int t = 0; t < TAGS; t++) g_feats[s * TAGS + t] = acc[t] + bsm[t];
    }
}

// ---------------- kernel 5: two-phase Viterbi (exact) ----------------
// Phase 1 (warp 0): lean sequential forward recursion — values only, no
// backpointers — checkpointing fv every VCH steps. fv depends only on
// max (exactly associative) + per-element adds, so the tree-max fv is
// bit-identical to the serial recursion.
// Phase 2 (32 warps): each warp replays its VCH-step chunk from the
// bit-exact checkpoint, computing backpointers with the identical per-step
// computation (equality mask + ffs = first argmax, matching jnp.argmax).
// Then terminal argmax + backtrack as before.
__global__ void __launch_bounds__(VNW * 32) viterbi_k(
    const float* __restrict__ trans, float* __restrict__ out, int out_size) {
    __shared__ unsigned char bp[SQ][TAGS];   // 40 KB backpointers
    __shared__ float ckpt[VNW][16];          // fv at chunk starts
    __shared__ float fvfin[16];              // final fv (after SQ steps)
    int tid = threadIdx.x;
    int w = tid >> 5;
    int n = tid & 31;

    float tr[TAGS];
#pragma unroll
    for (int p = 0; p < TAGS; p++) tr[p] = (n < TAGS) ? trans[n * TAGS + p] : NEGV;

    // ---- phase 1: sequential values pass (warp 0) ----
    if (w == 0) {
        float fv = (n == 8) ? 0.0f : NEGV;   // START = 8
        float fa = (n < TAGS) ? g_feats[0 * TAGS + n] : 0.0f;
        float fb = (n < TAGS) ? g_feats[1 * TAGS + n] : 0.0f;
        for (int t = 0; t < SQ; t++) {
            if ((t & (VCH - 1)) == 0 && n < TAGS) ckpt[t / VCH][n] = fv;
            float v[TAGS];
#pragma unroll
            for (int p = 0; p < TAGS; p++)
                v[p] = __shfl_sync(0xffffffffu, fv, p) + tr[p];
            float m = max10(v);
            float nf = m + fa;
            fa = fb;
            int tn = t + 2;
            if (n < TAGS && tn < SQ) fb = g_feats[tn * TAGS + n];
            fv = nf;
        }
        if (n < 16) fvfin[n] = (n < TAGS) ? fv : NEGV;
    }
    __syncthreads();

    // ---- phase 2: parallel backpointer replay (warp w -> chunk w) ----
    {
        int t0 = w * VCH;
        float fv = (n < TAGS) ? ckpt[w][n] : NEGV;
        float fa = (n < TAGS) ? g_feats[t0 * TAGS + n] : 0.0f;
        float fb = (n < TAGS) ? g_feats[(t0 + 1) * TAGS + n] : 0.0f;
        for (int t = t0; t < t0 + VCH; t++) {
            float v[TAGS];
#pragma unroll
            for (int p = 0; p < TAGS; p++)
                v[p] = __shfl_sync(0xffffffffu, fv, p) + tr[p];
            float m = max10(v);
            unsigned mk = 0;
#pragma unroll
            for (int p = 0; p < TAGS; p++) mk |= (v[p] == m) ? (1u << p) : 0u;
            int bi = __ffs(mk) - 1;          // first max = jnp.argmax tie-break
            if (n < TAGS) bp[t][n] = (unsigned char)bi;
            float nf = m + fa;
            fa = fb;
            int tn = t + 2;
            if (n < TAGS && tn < SQ) fb = g_feats[tn * TAGS + n];
            fv = nf;
        }
    }
    __syncthreads();

    // ---- terminal + backtrack (warp 0) ----
    if (w == 0) {
        float term = (n < TAGS) ? (fvfin[n] + trans[9 * TAGS + n]) : -3.4e38f;
        float bm = -3.4e38f;
        int bidx = 0;
#pragma unroll
        for (int p = 0; p < TAGS; p++) {
            float v = __shfl_sync(0xffffffffu, term, p);
            if (v > bm) { bm = v; bidx = p; }
        }
        if (n == 0) {
            int off = (out_size > SQ) ? 1 : 0;
            if (off) out[0] = bm;            // score first, then path
            int tag = bidx;
            for (int t = SQ - 1; t >= 0; t--) {
                out[off + t] = (float)tag;
                tag = bp[t][tag];
            }
        }
    }
}

// ---------------- launch ----------------
extern "C" void kernel_launch(void* const* d_in, const int* in_sizes, int n_in,
                              void* d_out, int out_size) {
    const int*   sent  = (const int*)d_in[0];
    const float* emb   = (const float*)d_in[1];
    const float* Wih_f = (const float*)d_in[2];
    const float* Whh_f = (const float*)d_in[3];
    const float* bih_f = (const float*)d_in[4];
    const float* bhh_f = (const float*)d_in[5];
    const float* Wih_b = (const float*)d_in[6];
    const float* Whh_b = (const float*)d_in[7];
    const float* bih_b = (const float*)d_in[8];
    const float* bhh_b = (const float*)d_in[9];
    const float* W_out = (const float*)d_in[10];
    const float* b_out = (const float*)d_in[11];
    const float* trans = (const float*)d_in[12];
    float* out = (float*)d_out;

    gather_k<<<(SQ * 64) / 256, 256>>>(sent, emb);
    xw_gemm_k<<<dim3(SQ / 64, NG / 64, 2), 256>>>(Wih_f, Wih_b, bih_f, bhh_f, bih_b, bhh_b);
    lstm_k<<<dim3(CL, 2, 1), 256>>>(Whh_f, Whh_b);
    feats_k<<<SQ / 8, 256>>>(W_out, b_out);   // 512 blocks x 8 warps = 4096 positions
    viterbi_k<<<1, VNW * 32>>>(trans, out, out_size);
}